// round 15
// baseline (speedup 1.0000x reference)
#include <cuda_runtime.h>
#include <math.h>

#define BB 2
#define NN 512
#define SS 384
#define ZC 128
#define HH 12
#define CC 16
#define PQn 4
#define PVn 8
#define HC 192      /* H*C   */
#define HPQ3 144    /* H*PQ*3*/
#define HPV3 288    /* H*PV*3*/
#define CATW 2112   /* H*(C+4PV+Z) */
#define PROJ_W 1152

#define WLC  0.5773502691896258f     /* sqrt(1/3) */
#define COEF 0.06804138174397717f    /* wL*wC/2, wC=sqrt(2/(9*PQ)) */

#define KSPLIT 3
#define KSLICE (CATW/KSPLIT)         /* 704 = 22*32 */

__device__ __align__(16) float g_q [BB*NN*HC];
__device__ __align__(16) float g_k [BB*NN*HC];
__device__ __align__(16) float g_v [BB*NN*HC];
__device__ __align__(16) float g_qp[BB*NN*HPQ3];
__device__ __align__(16) float g_kp[BB*NN*HPQ3];
__device__ __align__(16) float g_vp[BB*NN*HPV3];
__device__ __align__(16) float g_qq[BB*NN*HH];
__device__ __align__(16) float g_kk[BB*NN*HH];
__device__ __align__(16) float g_cat[BB*NN*CATW];
__device__ __align__(16) float g_wcat[SS*PROJ_W];
__device__ __align__(16) float g_wbT [HH*ZC];     // transposed Wb: [h][c]
__device__ __align__(16) float g_proj[BB*NN*PROJ_W];
__device__ __align__(16) float g_opart[KSPLIT*BB*NN*SS];
// bias, then (after k_qkatt) attention weights; layout [b, i, h, j] (25 MB)
__device__ __align__(16) float g_att[(size_t)BB*NN*HH*NN];

__device__ __forceinline__ float dot4(float4 a, float4 b) {
    return a.x*b.x + a.y*b.y + a.z*b.z + a.w*b.w;
}

// ---- packed f32x2 helpers ---------------------------------------------------
__device__ __forceinline__ void ffma2(unsigned long long& acc,
                                      unsigned long long a, unsigned long long b) {
    asm("fma.rn.f32x2 %0, %1, %2, %0;" : "+l"(acc) : "l"(a), "l"(b));
}
__device__ __forceinline__ unsigned long long mul2(unsigned long long a,
                                                   unsigned long long b) {
    unsigned long long r;
    asm("mul.rn.f32x2 %0, %1, %2;" : "=l"(r) : "l"(a), "l"(b));
    return r;
}
__device__ __forceinline__ unsigned long long pack2(float lo, float hi) {
    unsigned long long r;
    asm("mov.b64 %0, {%1, %2};" : "=l"(r) : "f"(lo), "f"(hi));
    return r;
}
__device__ __forceinline__ float hadd2(unsigned long long v) {
    float lo, hi;
    asm("mov.b64 {%0, %1}, %2;" : "=f"(lo), "=f"(hi) : "l"(v));
    return lo + hi;
}

// ---------------------------------------------------------------------------
// k_pack: Wq|Wk|Wv|Wqp|Wkp|Wvp -> g_wcat[384][1152]; also Wb^T -> g_wbT.
// ---------------------------------------------------------------------------
__global__ __launch_bounds__(256) void k_pack(
    const float* __restrict__ Wq, const float* __restrict__ Wk, const float* __restrict__ Wv,
    const float* __restrict__ Wqp, const float* __restrict__ Wkp, const float* __restrict__ Wvp,
    const float* __restrict__ Wb)
{
    const int idx = blockIdx.x*256 + threadIdx.x;
    const int si = idx / PROJ_W, col = idx % PROJ_W;
    float v;
    if      (col < 192) v = Wq [si*192 + col];
    else if (col < 384) v = Wk [si*192 + col - 192];
    else if (col < 576) v = Wv [si*192 + col - 384];
    else if (col < 720) v = Wqp[si*144 + col - 576];
    else if (col < 864) v = Wkp[si*144 + col - 720];
    else                v = Wvp[si*288 + col - 864];
    g_wcat[idx] = v;
    if (idx < HH*ZC) {
        const int h = idx >> 7, c = idx & 127;
        g_wbT[idx] = Wb[c*HH + h];
    }
}

// ---------------------------------------------------------------------------
// Generic tiled fp32 GEMM
// ---------------------------------------------------------------------------
template<int BM, int BN, int TM, int TN>
__global__ __launch_bounds__(256) void k_gemm(
    const float* __restrict__ A, int lda,
    const float* __restrict__ B, int ldb,
    float* __restrict__ C, int ldc, int K)
{
    constexpr int BK = 32;
    __shared__ float As[BK][BM + 1];
    __shared__ __align__(16) float Bs[BK][BN];
    const int tid = threadIdx.x;
    const int ncols = BN / TN;
    const int tr = tid / ncols;
    const int tc = tid % ncols;
    const int m0 = blockIdx.y * BM;
    const int n0 = blockIdx.x * BN;

    float acc[TM][TN];
    #pragma unroll
    for (int i = 0; i < TM; i++)
        #pragma unroll
        for (int j = 0; j < TN; j++) acc[i][j] = 0.f;

    for (int k0 = 0; k0 < K; k0 += BK) {
        #pragma unroll
        for (int r = 0; r < (BM*BK)/256; r++) {
            const int idx = tid + r*256;
            const int m = idx / BK, kk = idx % BK;
            As[kk][m] = A[(m0 + m)*lda + k0 + kk];
        }
        #pragma unroll
        for (int r = 0; r < (BN*BK)/256; r++) {
            const int idx = tid + r*256;
            const int kk = idx / BN, n = idx % BN;
            Bs[kk][n] = B[(k0 + kk)*ldb + n0 + n];
        }
        __syncthreads();
        #pragma unroll
        for (int kk = 0; kk < BK; kk++) {
            float a[TM];
            #pragma unroll
            for (int i = 0; i < TM; i++) a[i] = As[kk][tr*TM + i];
            const float4 b4 = *(const float4*)&Bs[kk][tc*TN];
            #pragma unroll
            for (int i = 0; i < TM; i++) {
                acc[i][0] = fmaf(a[i], b4.x, acc[i][0]);
                acc[i][1] = fmaf(a[i], b4.y, acc[i][1]);
                acc[i][2] = fmaf(a[i], b4.z, acc[i][2]);
                acc[i][3] = fmaf(a[i], b4.w, acc[i][3]);
            }
        }
        __syncthreads();
    }
    #pragma unroll
    for (int i = 0; i < TM; i++) {
        float4 v = make_float4(acc[i][0], acc[i][1], acc[i][2], acc[i][3]);
        *(float4*)&C[(m0 + tr*TM + i)*ldc + n0 + tc*TN] = v;
    }
}

// ---------------------------------------------------------------------------
// k_gemm_sk: split-K GEMM. blockIdx.z = K-slice. Partial -> g_opart.
// ---------------------------------------------------------------------------
__global__ __launch_bounds__(256) void k_gemm_sk(
    const float* __restrict__ A, const float* __restrict__ B)
{
    constexpr int BM = 32, BN = 64, BK = 32;
    __shared__ float As[BK][BM + 1];
    __shared__ __align__(16) float Bs[BK][BN];
    const int tid = threadIdx.x;
    const int tr = tid >> 4;
    const int tc = tid & 15;
    const int m0 = blockIdx.y * BM;
    const int n0 = blockIdx.x * BN;
    const int kb = blockIdx.z * KSLICE;

    float acc[2][4];
    #pragma unroll
    for (int i = 0; i < 2; i++)
        #pragma unroll
        for (int j = 0; j < 4; j++) acc[i][j] = 0.f;

    for (int k0 = 0; k0 < KSLICE; k0 += BK) {
        #pragma unroll
        for (int r = 0; r < 4; r++) {
            const int idx = tid + r*256;
            const int m = idx >> 5, kk = idx & 31;
            As[kk][m] = A[(size_t)(m0 + m)*CATW + kb + k0 + kk];
        }
        #pragma unroll
        for (int r = 0; r < 8; r++) {
            const int idx = tid + r*256;
            const int kk = idx >> 6, n = idx & 63;
            Bs[kk][n] = B[(size_t)(kb + k0 + kk)*SS + n0 + n];
        }
        __syncthreads();
        #pragma unroll
        for (int kk = 0; kk < BK; kk++) {
            const float a0 = As[kk][tr*2 + 0];
            const float a1 = As[kk][tr*2 + 1];
            const float4 b4 = *(const float4*)&Bs[kk][tc*4];
            acc[0][0] = fmaf(a0, b4.x, acc[0][0]);
            acc[0][1] = fmaf(a0, b4.y, acc[0][1]);
            acc[0][2] = fmaf(a0, b4.z, acc[0][2]);
            acc[0][3] = fmaf(a0, b4.w, acc[0][3]);
            acc[1][0] = fmaf(a1, b4.x, acc[1][0]);
            acc[1][1] = fmaf(a1, b4.y, acc[1][1]);
            acc[1][2] = fmaf(a1, b4.z, acc[1][2]);
            acc[1][3] = fmaf(a1, b4.w, acc[1][3]);
        }
        __syncthreads();
    }
    float* Cp = g_opart + (size_t)blockIdx.z * (BB*NN*SS);
    #pragma unroll
    for (int i = 0; i < 2; i++) {
        float4 v = make_float4(acc[i][0], acc[i][1], acc[i][2], acc[i][3]);
        *(float4*)&Cp[(size_t)(m0 + tr*2 + i)*SS + n0 + tc*4] = v;
    }
}

// ---------------------------------------------------------------------------
// k_outred: out = sum of KSPLIT partials (float4 granularity)
// ---------------------------------------------------------------------------
__global__ __launch_bounds__(256) void k_outred(float* __restrict__ out)
{
    const int idx = blockIdx.x*256 + threadIdx.x;
    const float4* p0 = (const float4*)g_opart;
    const float4* p1 = (const float4*)(g_opart + BB*NN*SS);
    const float4* p2 = (const float4*)(g_opart + 2*BB*NN*SS);
    const float4 a = p0[idx], b = p1[idx], c = p2[idx];
    float4 s;
    s.x = a.x + b.x + c.x;
    s.y = a.y + b.y + c.y;
    s.z = a.z + b.z + c.z;
    s.w = a.w + b.w + c.w;
    ((float4*)out)[idx] = s;
}

// ---------------------------------------------------------------------------
// k_projpost: frame transforms + point norms. One block per (b,n).
// ---------------------------------------------------------------------------
__global__ __launch_bounds__(128) void k_projpost(
    const float* __restrict__ R, const float* __restrict__ t)
{
    __shared__ float qq_sh[HH], kk_sh[HH];
    __shared__ float Rl[9], tl[3];
    const int bn  = blockIdx.x;
    const int tid = threadIdx.x;
    const float* proj = g_proj + bn*PROJ_W;

    if (tid < HH) { qq_sh[tid] = 0.f; kk_sh[tid] = 0.f; }
    if (tid < 9)  Rl[tid] = R[bn*9 + tid];
    if (tid < 3)  tl[tid] = t[bn*3 + tid];
    __syncthreads();

    for (int i = tid; i < HC; i += 128) {
        g_q[bn*HC + i] = proj[i];
        g_k[bn*HC + i] = proj[192 + i];
        g_v[bn*HC + i] = proj[384 + i];
    }
    if (tid < 96) {
        const int which = tid / 48;
        const int pt    = tid % 48;
        const int off   = which ? 720 : 576;
        const float px = proj[off + pt*3], py = proj[off + pt*3 + 1], pz = proj[off + pt*3 + 2];
        const float gx = Rl[0]*px + Rl[1]*py + Rl[2]*pz + tl[0];
        const float gy = Rl[3]*px + Rl[4]*py + Rl[5]*pz + tl[1];
        const float gz = Rl[6]*px + Rl[7]*py + Rl[8]*pz + tl[2];
        float* dst = (which ? g_kp : g_qp) + bn*HPQ3 + pt*3;
        dst[0] = gx; dst[1] = gy; dst[2] = gz;
        atomicAdd((which ? kk_sh : qq_sh) + pt/PQn, gx*gx + gy*gy + gz*gz);
    }
    if (tid < 96) {
        const int pt = tid;
        const float px = proj[864 + pt*3], py = proj[864 + pt*3 + 1], pz = proj[864 + pt*3 + 2];
        float* dst = g_vp + bn*HPV3 + pt*3;
        dst[0] = Rl[0]*px + Rl[1]*py + Rl[2]*pz + tl[0];
        dst[1] = Rl[3]*px + Rl[4]*py + Rl[5]*pz + tl[1];
        dst[2] = Rl[6]*px + Rl[7]*py + Rl[8]*pz + tl[2];
    }
    __syncthreads();
    if (tid < HH) { g_qq[bn*HH + tid] = qq_sh[tid]; g_kk[bn*HH + tid] = kk_sh[tid]; }
}

// ---------------------------------------------------------------------------
// k_bias v3: g_att[b,i,h,j] = sum_c z[b,i,j,c] * Wb[c,h].
// 256 threads, 16 rows/block (2 rows/thread), 32768 blocks.
// Lane = (hg = lane>>3: 3 heads, qt = lane&7: 16 channels).
// Wb slice in REGISTERS (48 floats from g_wbT, L1-warm). z staged coalesced
// with qt-stride-20 swizzle (bank-conflict-free). Partials via smem.
// ---------------------------------------------------------------------------
#define ZROWPAD 160   /* 8 qt-chunks x 20 floats */
__global__ __launch_bounds__(256) void k_bias(const float* __restrict__ z)
{
    __shared__ __align__(16) float z_s[16*ZROWPAD];   // 10240 B
    __shared__ __align__(16) float part[16*HH*8];     //  6144 B
    __shared__ __align__(16) float outbuf[HH*16];     //   768 B
    const int tid  = threadIdx.x;
    const int lane = tid & 31;
    const int w    = tid >> 5;            // 0..7 (row within half; rows w, w+8)
    const int hg   = lane >> 3;           // 0..3 -> heads hg*3..hg*3+2
    const int qt   = lane & 7;            // channels qt*16..qt*16+15
    const int row0 = blockIdx.x * 16;

    // Wb slice -> registers: 3 heads x 16 channels = 24 u64
    unsigned long long wv[3][8];
    #pragma unroll
    for (int hh = 0; hh < 3; hh++) {
        const float* wp = g_wbT + (hg*3 + hh)*ZC + qt*16;
        #pragma unroll
        for (int p = 0; p < 4; p++) {
            const ulonglong2 u = *(const ulonglong2*)(wp + p*4);
            wv[hh][p*2 + 0] = u.x;
            wv[hh][p*2 + 1] = u.y;
        }
    }

    // stage 16 z rows, coalesced, swizzled: channel c -> qt*20 + (c&15)
    #pragma unroll
    for (int k = 0; k < 2; k++) {
        const int idx = tid + k*256;          // float4 index, 512 total
        const int r = idx >> 5, c4 = idx & 31;
        const int q = c4 >> 2, p4 = c4 & 3;
        *(float4*)(z_s + r*ZROWPAD + q*20 + p4*4) =
            *(const float4*)(z + (size_t)row0*ZC + (size_t)idx*4);
    }
    __syncthreads();

    #pragma unroll
    for (int rr = 0; rr < 2; rr++) {
        const int row = w + rr*8;
        const float* zr = z_s + row*ZROWPAD + qt*20;
        const ulonglong2 za = *(const ulonglong2*)(zr + 0);
        const ulonglong2 zb = *(const ulonglong2*)(zr + 4);
        const ulonglong2 zc = *(const ulonglong2*)(zr + 8);
        const ulonglong2 zd = *(const ulonglong2*)(zr + 12);
        #pragma unroll
        for (int hh = 0; hh < 3; hh++) {
            unsigned long long a = mul2(za.x, wv[hh][0]);
            ffma2(a, za.y, wv[hh][1]);
            ffma2(a, zb.x, wv[hh][2]);
            ffma2(a, zb.y, wv[hh][3]);
            ffma2(a, zc.x, wv[hh][4]);
            ffma2(a, zc.y, wv[hh][5]);
            ffma2(a, zd.x, wv[hh][6]);
            ffma2(a, zd.y, wv[hh][7]);
            part[(row*HH + hg*3 + hh)*8 + qt] = hadd2(a);
        }
    }
    __syncthreads();

    // reduce 8 qt-partials per (row, head): 192 pairs
    if (tid < 16*HH) {
        const float4 p0 = *(const float4*)(part + tid*8);
        const float4 p1 = *(const float4*)(part + tid*8 + 4);
        const float s = ((p0.x + p0.y) + (p0.z + p0.w))
                      + ((p1.x + p1.y) + (p1.z + p1.w));
        const int row = tid / HH, h = tid % HH;
        outbuf[h*16 + row] = s;
    }
    __syncthreads();

    // coalesced store: 16 rows share (b,i); j spans a 16-aligned window
    const int bi = row0 >> 9;             // b*NN + i
    const int j0 = row0 & 511;
    if (tid < HH*4) {
        const int h = tid >> 2, q4 = tid & 3;
        *(float4*)(g_att + ((size_t)bi*HH + h)*NN + j0 + q4*4) =
            *(const float4*)(outbuf + h*16 + q4*4);
    }
}

// ---------------------------------------------------------------------------
// k_qkatt: per (b,h,i-tile32): logits tile [32,512] via [32x28]@[28x512] GEMM
// ---------------------------------------------------------------------------
#define QK_LOG  0          /* 32*512 = 16384 */
#define QK_A    16384      /* 32*28  =   896 */
#define QK_CI   17280      /* 32 */
#define QK_SMEM_FLOATS 17312
#define QK_SMEM_BYTES (QK_SMEM_FLOATS*4)

__global__ __launch_bounds__(256) void k_qkatt(const float* __restrict__ hw)
{
    extern __shared__ __align__(16) float qs[];
    float* lg   = qs + QK_LOG;
    float* A_s  = qs + QK_A;
    float* ci_s = qs + QK_CI;

    const int tid = threadIdx.x;
    const int b   = blockIdx.z;
    const int h   = blockIdx.y;
    const int i0  = blockIdx.x * 32;
    const float gch = COEF * log1pf(expf(hw[h]));

    for (int idx = tid; idx < 32*28; idx += 256) {
        const int r = idx / 28, c = idx % 28;
        float v;
        if (c < 16) v = (WLC*0.25f) * g_q [(b*NN + i0 + r)*HC   + h*CC + c];
        else        v = (2.f*gch)   * g_qp[(b*NN + i0 + r)*HPQ3 + h*12 + (c - 16)];
        A_s[idx] = v;
    }
    if (tid < 32) ci_s[tid] = -gch * g_qq[(b*NN + i0 + tid)*HH + h];
    __syncthreads();

    #pragma unroll
    for (int half = 0; half < 2; half++) {
        const int j = tid + half*256;
        float kb[28];
        {
            const float4* kr  = (const float4*)(g_k  + (b*NN + j)*HC   + h*CC);
            const float4* kpr = (const float4*)(g_kp + (b*NN + j)*HPQ3 + h*12);
            *(float4*)(kb +  0) = kr[0];
            *(float4*)(kb +  4) = kr[1];
            *(float4*)(kb +  8) = kr[2];
            *(float4*)(kb + 12) = kr[3];
            *(float4*)(kb + 16) = kpr[0];
            *(float4*)(kb + 20) = kpr[1];
            *(float4*)(kb + 24) = kpr[2];
        }
        const float dj = -gch * g_kk[(b*NN + j)*HH + h];

        float acc[32];
        #pragma unroll
        for (int r = 0; r < 32; r++) {
            const float4* Ar = (const float4*)(A_s + r*28);
            const float4 a0 = Ar[0], a1 = Ar[1], a2 = Ar[2], a3 = Ar[3];
            const float4 a4 = Ar[4], a5 = Ar[5], a6 = Ar[6];
            float s = a0.x*kb[0]  + a0.y*kb[1]  + a0.z*kb[2]  + a0.w*kb[3];
            s += a1.x*kb[4]  + a1.y*kb[5]  + a1.z*kb[6]  + a1.w*kb[7];
            s += a2.x*kb[8]  + a2.y*kb[9]  + a2.z*kb[10] + a2.w*kb[11];
            s += a3.x*kb[12] + a3.y*kb[13] + a3.z*kb[14] + a3.w*kb[15];
            s += a4.x*kb[16] + a4.y*kb[17] + a4.z*kb[18] + a4.w*kb[19];
            s += a5.x*kb[20] + a5.y*kb[21] + a5.z*kb[22] + a5.w*kb[23];
            s += a6.x*kb[24] + a6.y*kb[25] + a6.z*kb[26] + a6.w*kb[27];
            acc[r] = s;
        }
        #pragma unroll 8
        for (int r = 0; r < 32; r++) {
            const float bias = g_att[((size_t)(b*NN + i0 + r)*HH + h)*NN + j];
            lg[r*512 + j] = acc[r] + ci_s[r] + dj + WLC*bias;
        }
    }
    __syncthreads();

    {
        const int wid = tid >> 5, lane = tid & 31;
        for (int row = wid; row < 32; row += 8) {
            float* Lr = lg + row*512;
            float m = -1e30f;
            #pragma unroll 4
            for (int c = lane; c < 512; c += 32) m = fmaxf(m, Lr[c]);
            #pragma unroll
            for (int o = 16; o; o >>= 1) m = fmaxf(m, __shfl_xor_sync(0xffffffffu, m, o));
            float ssum = 0.f;
            #pragma unroll 4
            for (int c = lane; c < 512; c += 32) { const float e = __expf(Lr[c] - m); Lr[c] = e; ssum += e; }
            #pragma unroll
            for (int o = 16; o; o >>= 1) ssum += __shfl_xor_sync(0xffffffffu, ssum, o);
            const float inv = 1.f / ssum;
            #pragma unroll 4
            for (int c = lane; c < 512; c += 32) Lr[c] *= inv;
        }
    }
    __syncthreads();

    for (int r4 = tid; r4 < 32*128; r4 += 256) {
        const int r = r4 >> 7, c4 = r4 & 127;
        *(float4*)(g_att + ((size_t)(b*NN + i0 + r)*HH + h)*NN + c4*4) =
            *(const float4*)(lg + r*512 + c4*4);
    }
}

// ---------------------------------------------------------------------------
// k_ofin: per (b,i): opair = a@z, o = a@v, opt_g = a@vp, frame + norms.
// ---------------------------------------------------------------------------
#define F_AS    0
#define F_PART  6144
#define F_OG    12288
#define F_RS    12576
#define F_TS    12585
#define F_VPART 12588
#define FIN_SMEM_FLOATS 14508
#define FIN_SMEM_BYTES  (FIN_SMEM_FLOATS*4)

__global__ __launch_bounds__(512) void k_ofin(
    const float* __restrict__ z, const float* __restrict__ R,
    const float* __restrict__ t)
{
    extern __shared__ __align__(16) float sm[];
    float* a_s   = sm + F_AS;
    float* part  = sm + F_PART;
    float* og    = sm + F_OG;
    float* R_s   = sm + F_RS;
    float* t_s   = sm + F_TS;
    float* vpart = sm + F_VPART;

    const int tid = threadIdx.x;
    const int blk = blockIdx.x;
    const int b   = blk >> 9;
    const int i   = blk & 511;

    {
        float4* dst = (float4*)a_s;
        const float4* src = (const float4*)(g_att + (size_t)(b*NN + i)*HH*NN);
        #pragma unroll
        for (int r = 0; r < 3; r++) dst[tid + r*512] = src[tid + r*512];
    }
    if (tid < 9) R_s[tid] = R[(b*NN + i)*9 + tid];
    if (tid < 3) t_s[tid] = t[(b*NN + i)*3 + tid];
    __syncthreads();

    {
        const int q   = tid >> 7;
        const int col = tid & 127;
        unsigned long long acc2[HH];
        #pragma unroll
        for (int h = 0; h < HH; h++) acc2[h] = 0ull;
        const float* zb = z + ((size_t)(b*NN + i)*NN + q*128)*ZC + col;
        const float* ab = a_s + q*128;
        #pragma unroll 2
        for (int jj = 0; jj < 128; jj += 4) {
            const float z0 = zb[(size_t)(jj+0)*ZC];
            const float z1 = zb[(size_t)(jj+1)*ZC];
            const float z2 = zb[(size_t)(jj+2)*ZC];
            const float z3 = zb[(size_t)(jj+3)*ZC];
            const unsigned long long zpA = pack2(z0, z1);
            const unsigned long long zpB = pack2(z2, z3);
            #pragma unroll
            for (int h = 0; h < HH; h++) {
                const ulonglong2 av = *(const ulonglong2*)(ab + h*NN + jj);
                ffma2(acc2[h], av.x, zpA);
                ffma2(acc2[h], av.y, zpB);
            }
        }
        #pragma unroll
        for (int h = 0; h < HH; h++) part[(q*HH + h)*128 + col] = hadd2(acc2[h]);
    }

    if (tid < 480) {
        const int q = tid / 120;
        const int c = tid % 120;
        const float* src; int ld, h;
        if (c < 48) { src = g_v  + (size_t)b*NN*HC   + c*4;      ld = HC;   h = c >> 2; }
        else        { src = g_vp + (size_t)b*NN*HPV3 + (c-48)*4; ld = HPV3; h = (c-48) / 6; }
        const float* arow = a_s + h*NN + q*128;
        const float* srcq = src + (size_t)(q*128)*ld;
        float4 acc = make_float4(0.f, 0.f, 0.f, 0.f);
        #pragma unroll 2
        for (int jj4 = 0; jj4 < 32; jj4++) {
            const float4 a4 = *(const float4*)(arow + jj4*4);
            const float4 v0 = *(const float4*)(srcq + (size_t)(jj4*4+0)*ld);
            const float4 v1 = *(const float4*)(srcq + (size_t)(jj4*4+1)*ld);
            const float4 v2 = *(const float4*)(srcq + (size_t)(jj4*4+2)*ld);
            const float4 v3 = *(const float4*)(srcq + (size_t)(jj4*4+3)*ld);
            acc.x = fmaf(a4.x, v0.x, fmaf(a4.y, v1.x, fmaf(a4.z, v2.x, fmaf(a4.w, v3.x, acc.x))));
            acc.y = fmaf(a4.x, v0.y, fmaf(a4.y, v1.y, fmaf(a4.z, v2.y, fmaf(a4.w, v3.y, acc.y))));
            acc.z = fmaf(a4.x, v0.z, fmaf(a4.y, v1.z, fmaf(a4.z, v2.z, fmaf(a4.w, v3.z, acc.z))));
            acc.w = fmaf(a4.x, v0.w, fmaf(a4.y, v1.w, fmaf(a4.z, v2.w, fmaf(a4.w, v3.w, acc.w))));
        }
        *(float4*)(vpart + (q*120 + c)*4) = acc;
    }
    __syncthreads();

    for (int idx = tid; idx < HH*128; idx += 512) {
        const float s = part[idx] + part[1536 + idx] + part[2*1536 + idx] + part[3*1536 + idx];
        g_cat[(size_t)(b*NN + i)*CATW + 576 + idx] = s;
    }

    if (tid < 120) {
        const float4 p0 = *(const float4*)(vpart + (0*120 + tid)*4);
        const float4 p1 = *(const float4*)(vpart + (1*120 + tid)*4);
        const float4 p2 = *(const float4*)(vpart + (2*120 + tid)*4);
        const float4 p3 = *(const float4*)(vpart + (3*120 + tid)*4);
        float4 s;
        s.x = (p0.x + p1.x) + (p2.x + p3.x);
        s.y = (p0.y + p1.y) + (p2.y + p3.y);
        s.z = (p0.z + p1.z) + (p2.z + p3.z);
        s.w = (p0.w + p1.w) + (p2.w + p3.w);
        if (tid < 48) *(float4*)(g_cat + (size_t)(b*NN + i)*CATW + tid*4) = s;
        else          *(float4*)(og + (tid - 48)*4) = s;
    }
    __syncthreads();

    if (tid < 96) {
        const int hp = tid;
        const float dx = og[hp*3 + 0] - t_s[0];
        const float dy = og[hp*3 + 1] - t_s[1];
        const float dz = og[hp*3 + 2] - t_s[2];
        const float ox = R_s[0]*dx + R_s[3]*dy + R_s[6]*dz;
        const float oy = R_s[1]*dx + R_s[4]*dy + R_s[7]*dz;
        const float oz = R_s[2]*dx + R_s[5]*dy + R_s[8]*dz;
        float* cg = g_cat + (size_t)(b*NN + i)*CATW;
        cg[192 + hp*3 + 0] = ox;
        cg[192 + hp*3 + 1] = oy;
        cg[192 + hp*3 + 2] = oz;
        cg[480 + hp] = sqrtf(ox*ox + oy*oy + oz*oz + 1e-8f);
    }
}

// ---------------------------------------------------------------------------
extern "C" void kernel_launch(void* const* d_in, const int* in_sizes, int n_in,
                              void* d_out, int out_size)
{
    const float* s    = (const float*)d_in[0];
    const float* z    = (const float*)d_in[1];
    const float* R    = (const float*)d_in[2];
    const float* t    = (const float*)d_in[3];
    const float* Wq   = (const float*)d_in[4];
    const float* Wk   = (const float*)d_in[5];
    const float* Wv   = (const float*)d_in[6];
    const float* Wqp  = (const float*)d_in[7];
    const float* Wkp  = (const float*)d_in[8];
    const float* Wvp  = (const float*)d_in[9];
    const float* Wb   = (const float*)d_in[10];
    const float* hw   = (const float*)d_in[11];
    const float* Wout = (const float*)d_in[12];
    float* out = (float*)d_out;

    cudaFuncSetAttribute(k_qkatt, cudaFuncAttributeMaxDynamicSharedMemorySize, QK_SMEM_BYTES);
    cudaFuncSetAttribute(k_ofin,  cudaFuncAttributeMaxDynamicSharedMemorySize, FIN_SMEM_BYTES);

    float* g_wcat_p;  cudaGetSymbolAddress((void**)&g_wcat_p, g_wcat);
    float* g_proj_p;  cudaGetSymbolAddress((void**)&g_proj_p, g_proj);
    float* g_cat_p;   cudaGetSymbolAddress((void**)&g_cat_p,  g_cat);

    // projections (bias stays 4th launch for the ncu capture window)
    k_pack<<<(SS*PROJ_W)/256, 256>>>(Wq, Wk, Wv, Wqp, Wkp, Wvp, Wb);
    {
        dim3 grid(PROJ_W/64, (BB*NN)/64);
        k_gemm<64, 64, 4, 4><<<grid, 256>>>(s, SS, g_wcat_p, PROJ_W, g_proj_p, PROJ_W, SS);
    }
    k_projpost<<<BB*NN, 128>>>(R, t);

    // bias = z @ Wb (v3: staged z + reg-resident Wb slices)
    k_bias<<<(BB*NN*NN)/16, 256>>>(z);

    // logits-as-GEMM + softmax
    {
        dim3 grid(NN/32, HH, BB);
        k_qkatt<<<grid, 256, QK_SMEM_BYTES>>>(hw);
    }

    // opair + o + opt (z stream #2)
    k_ofin<<<BB*NN, 512, FIN_SMEM_BYTES>>>(z, R, t);

    // out = g_cat @ Wout via split-K=3 + reduce
    {
        dim3 grid(SS/64, (BB*NN)/32, KSPLIT);
        k_gemm_sk<<<grid, 256>>>(g_cat_p, Wout);
        k_outred<<<(BB*NN*SS/4)/256, 256>>>(out);
    }
}

// round 16
// speedup vs baseline: 1.2675x; 1.2675x over previous
#include <cuda_runtime.h>
#include <math.h>

#define BB 2
#define NN 512
#define SS 384
#define ZC 128
#define HH 12
#define CC 16
#define PQn 4
#define PVn 8
#define HC 192      /* H*C   */
#define HPQ3 144    /* H*PQ*3*/
#define HPV3 288    /* H*PV*3*/
#define CATW 2112   /* H*(C+4PV+Z) */
#define PROJ_W 1152

#define WLC  0.5773502691896258f     /* sqrt(1/3) */
#define COEF 0.06804138174397717f    /* wL*wC/2, wC=sqrt(2/(9*PQ)) */

#define KSPLIT 3
#define KSLICE (CATW/KSPLIT)         /* 704 = 22*32 */

__device__ __align__(16) float g_q [BB*NN*HC];
__device__ __align__(16) float g_k [BB*NN*HC];
__device__ __align__(16) float g_v [BB*NN*HC];
__device__ __align__(16) float g_qp[BB*NN*HPQ3];
__device__ __align__(16) float g_kp[BB*NN*HPQ3];
__device__ __align__(16) float g_vp[BB*NN*HPV3];
__device__ __align__(16) float g_qq[BB*NN*HH];
__device__ __align__(16) float g_kk[BB*NN*HH];
__device__ __align__(16) float g_cat[BB*NN*CATW];
__device__ __align__(16) float g_wcat[SS*PROJ_W];
__device__ __align__(16) float g_proj[BB*NN*PROJ_W];
__device__ __align__(16) float g_opart[KSPLIT*BB*NN*SS];
// bias, then (after k_qkatt) attention weights; layout [b, i, h, j] (25 MB)
__device__ __align__(16) float g_att[(size_t)BB*NN*HH*NN];

__device__ __forceinline__ float dot4(float4 a, float4 b) {
    return a.x*b.x + a.y*b.y + a.z*b.z + a.w*b.w;
}

// ---- packed f32x2 helpers ---------------------------------------------------
__device__ __forceinline__ void ffma2(unsigned long long& acc,
                                      unsigned long long a, unsigned long long b) {
    asm("fma.rn.f32x2 %0, %1, %2, %0;" : "+l"(acc) : "l"(a), "l"(b));
}
__device__ __forceinline__ unsigned long long pack2(float lo, float hi) {
    unsigned long long r;
    asm("mov.b64 %0, {%1, %2};" : "=l"(r) : "f"(lo), "f"(hi));
    return r;
}
__device__ __forceinline__ float hadd2(unsigned long long v) {
    float lo, hi;
    asm("mov.b64 {%0, %1}, %2;" : "=f"(lo), "=f"(hi) : "l"(v));
    return lo + hi;
}

// ---------------------------------------------------------------------------
// k_pack: Wq|Wk|Wv|Wqp|Wkp|Wvp -> g_wcat[384][1152]
// ---------------------------------------------------------------------------
__global__ __launch_bounds__(256) void k_pack(
    const float* __restrict__ Wq, const float* __restrict__ Wk, const float* __restrict__ Wv,
    const float* __restrict__ Wqp, const float* __restrict__ Wkp, const float* __restrict__ Wvp)
{
    const int idx = blockIdx.x*256 + threadIdx.x;
    const int si = idx / PROJ_W, col = idx % PROJ_W;
    float v;
    if      (col < 192) v = Wq [si*192 + col];
    else if (col < 384) v = Wk [si*192 + col - 192];
    else if (col < 576) v = Wv [si*192 + col - 384];
    else if (col < 720) v = Wqp[si*144 + col - 576];
    else if (col < 864) v = Wkp[si*144 + col - 720];
    else                v = Wvp[si*288 + col - 864];
    g_wcat[idx] = v;
}

// ---------------------------------------------------------------------------
// Generic tiled fp32 GEMM
// ---------------------------------------------------------------------------
template<int BM, int BN, int TM, int TN>
__global__ __launch_bounds__(256) void k_gemm(
    const float* __restrict__ A, int lda,
    const float* __restrict__ B, int ldb,
    float* __restrict__ C, int ldc, int K)
{
    constexpr int BK = 32;
    __shared__ float As[BK][BM + 1];
    __shared__ __align__(16) float Bs[BK][BN];
    const int tid = threadIdx.x;
    const int ncols = BN / TN;
    const int tr = tid / ncols;
    const int tc = tid % ncols;
    const int m0 = blockIdx.y * BM;
    const int n0 = blockIdx.x * BN;

    float acc[TM][TN];
    #pragma unroll
    for (int i = 0; i < TM; i++)
        #pragma unroll
        for (int j = 0; j < TN; j++) acc[i][j] = 0.f;

    for (int k0 = 0; k0 < K; k0 += BK) {
        #pragma unroll
        for (int r = 0; r < (BM*BK)/256; r++) {
            const int idx = tid + r*256;
            const int m = idx / BK, kk = idx % BK;
            As[kk][m] = A[(m0 + m)*lda + k0 + kk];
        }
        #pragma unroll
        for (int r = 0; r < (BN*BK)/256; r++) {
            const int idx = tid + r*256;
            const int kk = idx / BN, n = idx % BN;
            Bs[kk][n] = B[(k0 + kk)*ldb + n0 + n];
        }
        __syncthreads();
        #pragma unroll
        for (int kk = 0; kk < BK; kk++) {
            float a[TM];
            #pragma unroll
            for (int i = 0; i < TM; i++) a[i] = As[kk][tr*TM + i];
            const float4 b4 = *(const float4*)&Bs[kk][tc*TN];
            #pragma unroll
            for (int i = 0; i < TM; i++) {
                acc[i][0] = fmaf(a[i], b4.x, acc[i][0]);
                acc[i][1] = fmaf(a[i], b4.y, acc[i][1]);
                acc[i][2] = fmaf(a[i], b4.z, acc[i][2]);
                acc[i][3] = fmaf(a[i], b4.w, acc[i][3]);
            }
        }
        __syncthreads();
    }
    #pragma unroll
    for (int i = 0; i < TM; i++) {
        float4 v = make_float4(acc[i][0], acc[i][1], acc[i][2], acc[i][3]);
        *(float4*)&C[(m0 + tr*TM + i)*ldc + n0 + tc*TN] = v;
    }
}

// ---------------------------------------------------------------------------
// k_gemm_sk: split-K GEMM. blockIdx.z = K-slice. Partial -> g_opart.
// ---------------------------------------------------------------------------
__global__ __launch_bounds__(256) void k_gemm_sk(
    const float* __restrict__ A, const float* __restrict__ B)
{
    constexpr int BM = 32, BN = 64, BK = 32;
    __shared__ float As[BK][BM + 1];
    __shared__ __align__(16) float Bs[BK][BN];
    const int tid = threadIdx.x;
    const int tr = tid >> 4;
    const int tc = tid & 15;
    const int m0 = blockIdx.y * BM;
    const int n0 = blockIdx.x * BN;
    const int kb = blockIdx.z * KSLICE;

    float acc[2][4];
    #pragma unroll
    for (int i = 0; i < 2; i++)
        #pragma unroll
        for (int j = 0; j < 4; j++) acc[i][j] = 0.f;

    for (int k0 = 0; k0 < KSLICE; k0 += BK) {
        #pragma unroll
        for (int r = 0; r < 4; r++) {
            const int idx = tid + r*256;
            const int m = idx >> 5, kk = idx & 31;
            As[kk][m] = A[(size_t)(m0 + m)*CATW + kb + k0 + kk];
        }
        #pragma unroll
        for (int r = 0; r < 8; r++) {
            const int idx = tid + r*256;
            const int kk = idx >> 6, n = idx & 63;
            Bs[kk][n] = B[(size_t)(kb + k0 + kk)*SS + n0 + n];
        }
        __syncthreads();
        #pragma unroll
        for (int kk = 0; kk < BK; kk++) {
            const float a0 = As[kk][tr*2 + 0];
            const float a1 = As[kk][tr*2 + 1];
            const float4 b4 = *(const float4*)&Bs[kk][tc*4];
            acc[0][0] = fmaf(a0, b4.x, acc[0][0]);
            acc[0][1] = fmaf(a0, b4.y, acc[0][1]);
            acc[0][2] = fmaf(a0, b4.z, acc[0][2]);
            acc[0][3] = fmaf(a0, b4.w, acc[0][3]);
            acc[1][0] = fmaf(a1, b4.x, acc[1][0]);
            acc[1][1] = fmaf(a1, b4.y, acc[1][1]);
            acc[1][2] = fmaf(a1, b4.z, acc[1][2]);
            acc[1][3] = fmaf(a1, b4.w, acc[1][3]);
        }
        __syncthreads();
    }
    float* Cp = g_opart + (size_t)blockIdx.z * (BB*NN*SS);
    #pragma unroll
    for (int i = 0; i < 2; i++) {
        float4 v = make_float4(acc[i][0], acc[i][1], acc[i][2], acc[i][3]);
        *(float4*)&Cp[(size_t)(m0 + tr*2 + i)*SS + n0 + tc*4] = v;
    }
}

// ---------------------------------------------------------------------------
// k_outred: out = sum of KSPLIT partials (float4 granularity)
// ---------------------------------------------------------------------------
__global__ __launch_bounds__(256) void k_outred(float* __restrict__ out)
{
    const int idx = blockIdx.x*256 + threadIdx.x;
    const float4* p0 = (const float4*)g_opart;
    const float4* p1 = (const float4*)(g_opart + BB*NN*SS);
    const float4* p2 = (const float4*)(g_opart + 2*BB*NN*SS);
    const float4 a = p0[idx], b = p1[idx], c = p2[idx];
    float4 s;
    s.x = a.x + b.x + c.x;
    s.y = a.y + b.y + c.y;
    s.z = a.z + b.z + c.z;
    s.w = a.w + b.w + c.w;
    ((float4*)out)[idx] = s;
}

// ---------------------------------------------------------------------------
// k_projpost: frame transforms + point norms. One block per (b,n).
// ---------------------------------------------------------------------------
__global__ __launch_bounds__(128) void k_projpost(
    const float* __restrict__ R, const float* __restrict__ t)
{
    __shared__ float qq_sh[HH], kk_sh[HH];
    __shared__ float Rl[9], tl[3];
    const int bn  = blockIdx.x;
    const int tid = threadIdx.x;
    const float* proj = g_proj + bn*PROJ_W;

    if (tid < HH) { qq_sh[tid] = 0.f; kk_sh[tid] = 0.f; }
    if (tid < 9)  Rl[tid] = R[bn*9 + tid];
    if (tid < 3)  tl[tid] = t[bn*3 + tid];
    __syncthreads();

    for (int i = tid; i < HC; i += 128) {
        g_q[bn*HC + i] = proj[i];
        g_k[bn*HC + i] = proj[192 + i];
        g_v[bn*HC + i] = proj[384 + i];
    }
    if (tid < 96) {
        const int which = tid / 48;
        const int pt    = tid % 48;
        const int off   = which ? 720 : 576;
        const float px = proj[off + pt*3], py = proj[off + pt*3 + 1], pz = proj[off + pt*3 + 2];
        const float gx = Rl[0]*px + Rl[1]*py + Rl[2]*pz + tl[0];
        const float gy = Rl[3]*px + Rl[4]*py + Rl[5]*pz + tl[1];
        const float gz = Rl[6]*px + Rl[7]*py + Rl[8]*pz + tl[2];
        float* dst = (which ? g_kp : g_qp) + bn*HPQ3 + pt*3;
        dst[0] = gx; dst[1] = gy; dst[2] = gz;
        atomicAdd((which ? kk_sh : qq_sh) + pt/PQn, gx*gx + gy*gy + gz*gz);
    }
    if (tid < 96) {
        const int pt = tid;
        const float px = proj[864 + pt*3], py = proj[864 + pt*3 + 1], pz = proj[864 + pt*3 + 2];
        float* dst = g_vp + bn*HPV3 + pt*3;
        dst[0] = Rl[0]*px + Rl[1]*py + Rl[2]*pz + tl[0];
        dst[1] = Rl[3]*px + Rl[4]*py + Rl[5]*pz + tl[1];
        dst[2] = Rl[6]*px + Rl[7]*py + Rl[8]*pz + tl[2];
    }
    __syncthreads();
    if (tid < HH) { g_qq[bn*HH + tid] = qq_sh[tid]; g_kk[bn*HH + tid] = kk_sh[tid]; }
}

// ---------------------------------------------------------------------------
// k_bias: g_att[b,i,h,j] = sum_c z[b,i,j,c] * Wb[c,h].  z stream #1.
// R10 structure with conflict-free lane remap:
//   warp covers 8 rows x 4 head-groups (r = w*8 + (lane&7), hg = lane>>3):
//   zv row addresses -> 8 disjoint bank-quads (broadcast x4); wv padded to
//   stride 132 -> 4 hg addresses on disjoint banks. Both LDS streams clean.
// 64 rows/block, 256 threads, 8192 blocks.
// ---------------------------------------------------------------------------
#define BT_ROWS 64
__global__ __launch_bounds__(256) void k_bias(
    const float* __restrict__ z, const float* __restrict__ Wb)
{
    __shared__ __align__(16) float z_s[BT_ROWS*132];
    __shared__ __align__(16) float wb_s[HH*132];   // padded: wb_s[h*132+c]
    const int tid  = threadIdx.x;
    const int lane = tid & 31;
    const int w    = tid >> 5;                     // 0..7
    const int r0   = blockIdx.x * BT_ROWS;

    for (int idx = tid; idx < HH*ZC; idx += 256) {
        const int c = idx / HH, h = idx % HH;
        wb_s[h*132 + c] = Wb[idx];
    }
    for (int idx = tid; idx < BT_ROWS*ZC/4; idx += 256) {
        const int r = idx >> 5, c4 = idx & 31;
        *(float4*)(z_s + r*132 + c4*4) = *(const float4*)(z + (size_t)r0*ZC + (size_t)idx*4);
    }
    __syncthreads();

    const int hg = lane >> 3;          // 0..3, 3 heads each
    const int r  = w*8 + (lane & 7);   // 0..63
    unsigned long long acc2[3] = {0ull, 0ull, 0ull};
    const float* zr = z_s + r*132;
    #pragma unroll 8
    for (int c4 = 0; c4 < 32; c4++) {
        const ulonglong2 zv = *(const ulonglong2*)(zr + c4*4);
        #pragma unroll
        for (int hh = 0; hh < 3; hh++) {
            const ulonglong2 wv = *(const ulonglong2*)(wb_s + (hg*3 + hh)*132 + c4*4);
            ffma2(acc2[hh], zv.x, wv.x);
            ffma2(acc2[hh], zv.y, wv.y);
        }
    }
    const int row = r0 + r;
    const int b = row >> 18, rem = row & 262143;
    const int i = rem >> 9,  j   = rem & 511;
    float* dst = g_att + ((size_t)(b*NN + i)*HH + hg*3)*NN + j;
    #pragma unroll
    for (int hh = 0; hh < 3; hh++) dst[(size_t)hh*NN] = hadd2(acc2[hh]);
}

// ---------------------------------------------------------------------------
// k_qkatt: per (b,h,i-tile32): logits tile [32,512] via [32x28]@[28x512] GEMM
// ---------------------------------------------------------------------------
#define QK_LOG  0          /* 32*512 = 16384 */
#define QK_A    16384      /* 32*28  =   896 */
#define QK_CI   17280      /* 32 */
#define QK_SMEM_FLOATS 17312
#define QK_SMEM_BYTES (QK_SMEM_FLOATS*4)

__global__ __launch_bounds__(256) void k_qkatt(const float* __restrict__ hw)
{
    extern __shared__ __align__(16) float qs[];
    float* lg   = qs + QK_LOG;
    float* A_s  = qs + QK_A;
    float* ci_s = qs + QK_CI;

    const int tid = threadIdx.x;
    const int b   = blockIdx.z;
    const int h   = blockIdx.y;
    const int i0  = blockIdx.x * 32;
    const float gch = COEF * log1pf(expf(hw[h]));

    for (int idx = tid; idx < 32*28; idx += 256) {
        const int r = idx / 28, c = idx % 28;
        float v;
        if (c < 16) v = (WLC*0.25f) * g_q [(b*NN + i0 + r)*HC   + h*CC + c];
        else        v = (2.f*gch)   * g_qp[(b*NN + i0 + r)*HPQ3 + h*12 + (c - 16)];
        A_s[idx] = v;
    }
    if (tid < 32) ci_s[tid] = -gch * g_qq[(b*NN + i0 + tid)*HH + h];
    __syncthreads();

    #pragma unroll
    for (int half = 0; half < 2; half++) {
        const int j = tid + half*256;
        float kb[28];
        {
            const float4* kr  = (const float4*)(g_k  + (b*NN + j)*HC   + h*CC);
            const float4* kpr = (const float4*)(g_kp + (b*NN + j)*HPQ3 + h*12);
            *(float4*)(kb +  0) = kr[0];
            *(float4*)(kb +  4) = kr[1];
            *(float4*)(kb +  8) = kr[2];
            *(float4*)(kb + 12) = kr[3];
            *(float4*)(kb + 16) = kpr[0];
            *(float4*)(kb + 20) = kpr[1];
            *(float4*)(kb + 24) = kpr[2];
        }
        const float dj = -gch * g_kk[(b*NN + j)*HH + h];

        float acc[32];
        #pragma unroll
        for (int r = 0; r < 32; r++) {
            const float4* Ar = (const float4*)(A_s + r*28);
            const float4 a0 = Ar[0], a1 = Ar[1], a2 = Ar[2], a3 = Ar[3];
            const float4 a4 = Ar[4], a5 = Ar[5], a6 = Ar[6];
            float s = a0.x*kb[0]  + a0.y*kb[1]  + a0.z*kb[2]  + a0.w*kb[3];
            s += a1.x*kb[4]  + a1.y*kb[5]  + a1.z*kb[6]  + a1.w*kb[7];
            s += a2.x*kb[8]  + a2.y*kb[9]  + a2.z*kb[10] + a2.w*kb[11];
            s += a3.x*kb[12] + a3.y*kb[13] + a3.z*kb[14] + a3.w*kb[15];
            s += a4.x*kb[16] + a4.y*kb[17] + a4.z*kb[18] + a4.w*kb[19];
            s += a5.x*kb[20] + a5.y*kb[21] + a5.z*kb[22] + a5.w*kb[23];
            s += a6.x*kb[24] + a6.y*kb[25] + a6.z*kb[26] + a6.w*kb[27];
            acc[r] = s;
        }
        #pragma unroll 8
        for (int r = 0; r < 32; r++) {
            const float bias = g_att[((size_t)(b*NN + i0 + r)*HH + h)*NN + j];
            lg[r*512 + j] = acc[r] + ci_s[r] + dj + WLC*bias;
        }
    }
    __syncthreads();

    {
        const int wid = tid >> 5, lane = tid & 31;
        for (int row = wid; row < 32; row += 8) {
            float* Lr = lg + row*512;
            float m = -1e30f;
            #pragma unroll 4
            for (int c = lane; c < 512; c += 32) m = fmaxf(m, Lr[c]);
            #pragma unroll
            for (int o = 16; o; o >>= 1) m = fmaxf(m, __shfl_xor_sync(0xffffffffu, m, o));
            float ssum = 0.f;
            #pragma unroll 4
            for (int c = lane; c < 512; c += 32) { const float e = __expf(Lr[c] - m); Lr[c] = e; ssum += e; }
            #pragma unroll
            for (int o = 16; o; o >>= 1) ssum += __shfl_xor_sync(0xffffffffu, ssum, o);
            const float inv = 1.f / ssum;
            #pragma unroll 4
            for (int c = lane; c < 512; c += 32) Lr[c] *= inv;
        }
    }
    __syncthreads();

    for (int r4 = tid; r4 < 32*128; r4 += 256) {
        const int r = r4 >> 7, c4 = r4 & 127;
        *(float4*)(g_att + ((size_t)(b*NN + i0 + r)*HH + h)*NN + c4*4) =
            *(const float4*)(lg + r*512 + c4*4);
    }
}

// ---------------------------------------------------------------------------
// k_ofin: per (b,i): opair = a@z, o = a@v, opt_g = a@vp, frame + norms.
// ---------------------------------------------------------------------------
#define F_AS    0
#define F_PART  6144
#define F_OG    12288
#define F_RS    12576
#define F_TS    12585
#define F_VPART 12588
#define FIN_SMEM_FLOATS 14508
#define FIN_SMEM_BYTES  (FIN_SMEM_FLOATS*4)

__global__ __launch_bounds__(512) void k_ofin(
    const float* __restrict__ z, const float* __restrict__ R,
    const float* __restrict__ t)
{
    extern __shared__ __align__(16) float sm[];
    float* a_s   = sm + F_AS;
    float* part  = sm + F_PART;
    float* og    = sm + F_OG;
    float* R_s   = sm + F_RS;
    float* t_s   = sm + F_TS;
    float* vpart = sm + F_VPART;

    const int tid = threadIdx.x;
    const int blk = blockIdx.x;
    const int b   = blk >> 9;
    const int i   = blk & 511;

    {
        float4* dst = (float4*)a_s;
        const float4* src = (const float4*)(g_att + (size_t)(b*NN + i)*HH*NN);
        #pragma unroll
        for (int r = 0; r < 3; r++) dst[tid + r*512] = src[tid + r*512];
    }
    if (tid < 9) R_s[tid] = R[(b*NN + i)*9 + tid];
    if (tid < 3) t_s[tid] = t[(b*NN + i)*3 + tid];
    __syncthreads();

    {
        const int q   = tid >> 7;
        const int col = tid & 127;
        unsigned long long acc2[HH];
        #pragma unroll
        for (int h = 0; h < HH; h++) acc2[h] = 0ull;
        const float* zb = z + ((size_t)(b*NN + i)*NN + q*128)*ZC + col;
        const float* ab = a_s + q*128;
        #pragma unroll 2
        for (int jj = 0; jj < 128; jj += 4) {
            const float z0 = zb[(size_t)(jj+0)*ZC];
            const float z1 = zb[(size_t)(jj+1)*ZC];
            const float z2 = zb[(size_t)(jj+2)*ZC];
            const float z3 = zb[(size_t)(jj+3)*ZC];
            const unsigned long long zpA = pack2(z0, z1);
            const unsigned long long zpB = pack2(z2, z3);
            #pragma unroll
            for (int h = 0; h < HH; h++) {
                const ulonglong2 av = *(const ulonglong2*)(ab + h*NN + jj);
                ffma2(acc2[h], av.x, zpA);
                ffma2(acc2[h], av.y, zpB);
            }
        }
        #pragma unroll
        for (int h = 0; h < HH; h++) part[(q*HH + h)*128 + col] = hadd2(acc2[h]);
    }

    if (tid < 480) {
        const int q = tid / 120;
        const int c = tid % 120;
        const float* src; int ld, h;
        if (c < 48) { src = g_v  + (size_t)b*NN*HC   + c*4;      ld = HC;   h = c >> 2; }
        else        { src = g_vp + (size_t)b*NN*HPV3 + (c-48)*4; ld = HPV3; h = (c-48) / 6; }
        const float* arow = a_s + h*NN + q*128;
        const float* srcq = src + (size_t)(q*128)*ld;
        float4 acc = make_float4(0.f, 0.f, 0.f, 0.f);
        #pragma unroll 2
        for (int jj4 = 0; jj4 < 32; jj4++) {
            const float4 a4 = *(const float4*)(arow + jj4*4);
            const float4 v0 = *(const float4*)(srcq + (size_t)(jj4*4+0)*ld);
            const float4 v1 = *(const float4*)(srcq + (size_t)(jj4*4+1)*ld);
            const float4 v2 = *(const float4*)(srcq + (size_t)(jj4*4+2)*ld);
            const float4 v3 = *(const float4*)(srcq + (size_t)(jj4*4+3)*ld);
            acc.x = fmaf(a4.x, v0.x, fmaf(a4.y, v1.x, fmaf(a4.z, v2.x, fmaf(a4.w, v3.x, acc.x))));
            acc.y = fmaf(a4.x, v0.y, fmaf(a4.y, v1.y, fmaf(a4.z, v2.y, fmaf(a4.w, v3.y, acc.y))));
            acc.z = fmaf(a4.x, v0.z, fmaf(a4.y, v1.z, fmaf(a4.z, v2.z, fmaf(a4.w, v3.z, acc.z))));
            acc.w = fmaf(a4.x, v0.w, fmaf(a4.y, v1.w, fmaf(a4.z, v2.w, fmaf(a4.w, v3.w, acc.w))));
        }
        *(float4*)(vpart + (q*120 + c)*4) = acc;
    }
    __syncthreads();

    for (int idx = tid; idx < HH*128; idx += 512) {
        const float s = part[idx] + part[1536 + idx] + part[2*1536 + idx] + part[3*1536 + idx];
        g_cat[(size_t)(b*NN + i)*CATW + 576 + idx] = s;
    }

    if (tid < 120) {
        const float4 p0 = *(const float4*)(vpart + (0*120 + tid)*4);
        const float4 p1 = *(const float4*)(vpart + (1*120 + tid)*4);
        const float4 p2 = *(const float4*)(vpart + (2*120 + tid)*4);
        const float4 p3 = *(const float4*)(vpart + (3*120 + tid)*4);
        float4 s;
        s.x = (p0.x + p1.x) + (p2.x + p3.x);
        s.y = (p0.y + p1.y) + (p2.y + p3.y);
        s.z = (p0.z + p1.z) + (p2.z + p3.z);
        s.w = (p0.w + p1.w) + (p2.w + p3.w);
        if (tid < 48) *(float4*)(g_cat + (size_t)(b*NN + i)*CATW + tid*4) = s;
        else          *(float4*)(og + (tid - 48)*4) = s;
    }
    __syncthreads();

    if (tid < 96) {
        const int hp = tid;
        const float dx = og[hp*3 + 0] - t_s[0];
        const float dy = og[hp*3 + 1] - t_s[1];
        const float dz = og[hp*3 + 2] - t_s[2];
        const float ox = R_s[0]*dx + R_s[3]*dy + R_s[6]*dz;
        const float oy = R_s[1]*dx + R_s[4]*dy + R_s[7]*dz;
        const float oz = R_s[2]*dx + R_s[5]*dy + R_s[8]*dz;
        float* cg = g_cat + (size_t)(b*NN + i)*CATW;
        cg[192 + hp*3 + 0] = ox;
        cg[192 + hp*3 + 1] = oy;
        cg[192 + hp*3 + 2] = oz;
        cg[480 + hp] = sqrtf(ox*ox + oy*oy + oz*oz + 1e-8f);
    }
}

// ---------------------------------------------------------------------------
extern "C" void kernel_launch(void* const* d_in, const int* in_sizes, int n_in,
                              void* d_out, int out_size)
{
    const float* s    = (const float*)d_in[0];
    const float* z    = (const float*)d_in[1];
    const float* R    = (const float*)d_in[2];
    const float* t    = (const float*)d_in[3];
    const float* Wq   = (const float*)d_in[4];
    const float* Wk   = (const float*)d_in[5];
    const float* Wv   = (const float*)d_in[6];
    const float* Wqp  = (const float*)d_in[7];
    const float* Wkp  = (const float*)d_in[8];
    const float* Wvp  = (const float*)d_in[9];
    const float* Wb   = (const float*)d_in[10];
    const float* hw   = (const float*)d_in[11];
    const float* Wout = (const float*)d_in[12];
    float* out = (float*)d_out;

    cudaFuncSetAttribute(k_qkatt, cudaFuncAttributeMaxDynamicSharedMemorySize, QK_SMEM_BYTES);
    cudaFuncSetAttribute(k_ofin,  cudaFuncAttributeMaxDynamicSharedMemorySize, FIN_SMEM_BYTES);

    float* g_wcat_p;  cudaGetSymbolAddress((void**)&g_wcat_p, g_wcat);
    float* g_proj_p;  cudaGetSymbolAddress((void**)&g_proj_p, g_proj);
    float* g_cat_p;   cudaGetSymbolAddress((void**)&g_cat_p,  g_cat);

    // projections (bias stays 4th launch for the ncu capture window)
    k_pack<<<(SS*PROJ_W)/256, 256>>>(Wq, Wk, Wv, Wqp, Wkp, Wvp);
    {
        dim3 grid(PROJ_W/64, (BB*NN)/64);
        k_gemm<64, 64, 4, 4><<<grid, 256>>>(s, SS, g_wcat_p, PROJ_W, g_proj_p, PROJ_W, SS);
    }
    k_projpost<<<BB*NN, 128>>>(R, t);

    // bias = z @ Wb (R10 structure, conflict-free lane remap)
    k_bias<<<(BB*NN*NN)/BT_ROWS, 256>>>(z, Wb);

    // logits-as-GEMM + softmax
    {
        dim3 grid(NN/32, HH, BB);
        k_qkatt<<<grid, 256, QK_SMEM_BYTES>>>(hw);
    }

    // opair + o + opt (z stream #2)
    k_ofin<<<BB*NN, 512, FIN_SMEM_BYTES>>>(z, R, t);

    // out = g_cat @ Wout via split-K=3 + reduce
    {
        dim3 grid(SS/64, (BB*NN)/32, KSPLIT);
        k_gemm_sk<<<grid, 256>>>(g_cat_p, Wout);
        k_outred<<<(BB*NN*SS/4)/256, 256>>>(out);
    }
}